// round 15
// baseline (speedup 1.0000x reference)
#include <cuda_runtime.h>
#include <cuda_fp16.h>

#define N_NODES 100000
#define N_EDGES 3200000
#define NFEAT   128
#define F1      16
#define F2      4
#define F3      2
#define NC      8
#define CAP     64           // padded CSR row capacity (deg ~ Poisson(32))
#define OVFCAP  8192
#define FULL    0xffffffffu

#define T       256
#define EBLK    (N_EDGES / 4 / T)          // 3125 edge blocks (4 edges/thread)
#define GBLK    ((N_NODES + T - 1) / T)    // 391 gemm blocks

// ---------------- scratch (device globals; no allocation allowed) ----------
// g_cnt / g_ovf_cnt are zero at module load and re-zeroed by k_pull3 each run.
__device__ int g_ovf_cnt;
__device__ __align__(16) int    g_cnt[N_NODES];
__device__ __align__(16) int    g_pcsr[N_NODES * CAP];   // padded CSR: src ids
__device__ __align__(16) int2   g_ovf[OVFCAP];           // (dst, src) overflow
__device__ __align__(16) float  g_y1raw[N_NODES * F1];   // h@W1 (fp32, unscaled)
__device__ __align__(16) uint2  g_y1h[N_NODES * 4];      // (h@W1)*dinv, fp16
__device__ __align__(16) uint2  g_y2h[N_NODES];          // xw2*dinv, fp16
__device__ __align__(16) float2 g_y3[N_NODES];           // xw3*dinv, fp32

__device__ __forceinline__ float tanh_ap(float x) {
    float y;
    asm("tanh.approx.f32 %0, %1;" : "=f"(y) : "f"(x));
    return y;
}
__device__ __forceinline__ float4 h4_to_f4(uint2 r) {
    __half2 p0 = *reinterpret_cast<__half2*>(&r.x);
    __half2 p1 = *reinterpret_cast<__half2*>(&r.y);
    float2 f0 = __half22float2(p0);
    float2 f1 = __half22float2(p1);
    return make_float4(f0.x, f0.y, f1.x, f1.y);
}
__device__ __forceinline__ uint2 f4_to_h4(float a, float b, float c, float d) {
    __half2 p0 = __floats2half2_rn(a, b);
    __half2 p1 = __floats2half2_rn(c, d);
    uint2 r;
    r.x = *reinterpret_cast<unsigned*>(&p0);
    r.y = *reinterpret_cast<unsigned*>(&p1);
    return r;
}

// ---------------- K1: FUSED edge/CSR build + GEMM (spatial block split) -----
// Blocks [0, EBLK): padded-CSR build with inline dtype detect, 4 edges/thread.
// Blocks [EBLK, EBLK+GBLK): y1raw = h @ W1. Independent work, disjoint pipes.
__global__ void k_prep(const void* __restrict__ ei,
                       const float* __restrict__ h, const float* __restrict__ W1) {
    __shared__ float sW[NFEAT * F1];   // 8 KB (used by gemm blocks only)

    if (blockIdx.x < EBLK) {
        // ---- edge path ----
        unsigned nz = 0;
        {
            const unsigned* w = (const unsigned*)ei;
            for (int k = threadIdx.x; k < 2048; k += blockDim.x) nz |= w[2 * k + 1];
        }
        int is64 = !__syncthreads_or(nz != 0);

        int e4 = blockIdx.x * blockDim.x + threadIdx.x;
        int s0, s1, s2, s3, d0, d1, d2, d3;
        if (is64) {
            const longlong2* ps = (const longlong2*)ei;
            const longlong2* pd = ps + N_EDGES / 2;
            longlong2 a = ps[2 * e4], b = ps[2 * e4 + 1];
            longlong2 c = pd[2 * e4], d = pd[2 * e4 + 1];
            s0 = (int)a.x; s1 = (int)a.y; s2 = (int)b.x; s3 = (int)b.y;
            d0 = (int)c.x; d1 = (int)c.y; d2 = (int)d.x; d3 = (int)d.y;
        } else {
            const int4* ps = (const int4*)ei;
            const int4* pd = ps + N_EDGES / 4;
            int4 a = ps[e4], c = pd[e4];
            s0 = a.x; s1 = a.y; s2 = a.z; s3 = a.w;
            d0 = c.x; d1 = c.y; d2 = c.z; d3 = c.w;
        }
        int r0 = atomicAdd(&g_cnt[d0], 1);
        int r1 = atomicAdd(&g_cnt[d1], 1);
        int r2 = atomicAdd(&g_cnt[d2], 1);
        int r3 = atomicAdd(&g_cnt[d3], 1);
#define PUT(S, D, R) do {                                       \
        if ((R) < CAP) g_pcsr[(D) * CAP + (R)] = (S);           \
        else {                                                  \
            int q = atomicAdd(&g_ovf_cnt, 1);                   \
            if (q < OVFCAP) g_ovf[q] = make_int2(D, S);         \
        } } while (0)
        PUT(s0, d0, r0); PUT(s1, d1, r1); PUT(s2, d2, r2); PUT(s3, d3, r3);
#undef PUT
        return;
    }

    // ---- gemm path ----
    for (int i = threadIdx.x; i < NFEAT * F1; i += blockDim.x) sW[i] = W1[i];
    __syncthreads();

    int n = (blockIdx.x - EBLK) * blockDim.x + threadIdx.x;
    if (n >= N_NODES) return;

    float acc[F1];
#pragma unroll
    for (int f = 0; f < F1; f++) acc[f] = 0.0f;

    const float4* h4 = reinterpret_cast<const float4*>(h + (size_t)n * NFEAT);
#pragma unroll 4
    for (int k4 = 0; k4 < NFEAT / 4; k4++) {
        float4 hv = h4[k4];
        const float* w = &sW[(k4 * 4) * F1];
#pragma unroll
        for (int f = 0; f < F1; f++) {
            float a = acc[f];
            a = fmaf(hv.x, w[f],          a);
            a = fmaf(hv.y, w[F1 + f],     a);
            a = fmaf(hv.z, w[2 * F1 + f], a);
            a = fmaf(hv.w, w[3 * F1 + f], a);
            acc[f] = a;
        }
    }
    float4* o = reinterpret_cast<float4*>(g_y1raw + n * F1);
#pragma unroll
    for (int q = 0; q < F1 / 4; q++)
        o[q] = make_float4(acc[4 * q], acc[4 * q + 1], acc[4 * q + 2], acc[4 * q + 3]);
}

// ---------------- K2: y1h = fp16(y1raw * dinv), 2 threads/node (PDL) --------
__global__ void k_scale() {
    cudaGridDependencySynchronize();
    int t = blockIdx.x * blockDim.x + threadIdx.x;   // 2*N_NODES threads
    int n = t >> 1;
    int hh = t & 1;
    if (n >= N_NODES) return;
    float dinv = rsqrtf((float)(g_cnt[n] + 1));
    const float4* r = reinterpret_cast<const float4*>(g_y1raw + n * F1 + hh * 8);
    float4 v0 = r[0];
    float4 v1 = r[1];
    g_y1h[n * 4 + hh * 2 + 0] = f4_to_h4(v0.x * dinv, v0.y * dinv, v0.z * dinv, v0.w * dinv);
    g_y1h[n * 4 + hh * 2 + 1] = f4_to_h4(v1.x * dinv, v1.y * dinv, v1.z * dinv, v1.w * dinv);
}

// ---------------- K3: pull layer-1 + fused (tanh) + @W2 (PDL) --------------
// 8 lanes per node = 2 edge-slots x 4 feature-quarters; fp16 gathers, unroll2.
__global__ void k_pull1(const float* __restrict__ b1, const float* __restrict__ W2) {
    __shared__ float sW2[F1 * F2];
    __shared__ float sb1[F1];
    // weights are harness inputs, independent of the predecessor kernel —
    // stage them BEFORE the grid-dependency sync to overlap with its tail.
    for (int i = threadIdx.x; i < F1 * F2; i += blockDim.x) sW2[i] = W2[i];
    for (int i = threadIdx.x; i < F1; i += blockDim.x) sb1[i] = b1[i];
    __syncthreads();
    cudaGridDependencySynchronize();

    int t = blockIdx.x * blockDim.x + threadIdx.x;   // exactly N_NODES*8 threads
    int n = t >> 3;
    int j = t & 7;
    int s = j >> 2;       // edge slot 0/1
    int q = j & 3;        // feature quarter

    int cnt = g_cnt[n];
    int lim = min(cnt, CAP);
    int off = n * CAP;

    float a0 = 0.0f, a1 = 0.0f, a2 = 0.0f, a3 = 0.0f;
    float b0 = 0.0f, b1r = 0.0f, b2r = 0.0f, b3r = 0.0f;
    int i = off + s;
    int end = off + lim;
    for (; i + 2 < end; i += 4) {
        int src0 = __ldg(&g_pcsr[i]);
        int src1 = __ldg(&g_pcsr[i + 2]);
        float4 v0 = h4_to_f4(__ldg(&g_y1h[src0 * 4 + q]));
        float4 v1 = h4_to_f4(__ldg(&g_y1h[src1 * 4 + q]));
        a0 += v0.x; a1 += v0.y; a2 += v0.z; a3 += v0.w;
        b0 += v1.x; b1r += v1.y; b2r += v1.z; b3r += v1.w;
    }
    if (i < end) {
        int src = __ldg(&g_pcsr[i]);
        float4 v = h4_to_f4(__ldg(&g_y1h[src * 4 + q]));
        a0 += v.x; a1 += v.y; a2 += v.z; a3 += v.w;
    }
    a0 += b0; a1 += b1r; a2 += b2r; a3 += b3r;

    int oc = g_ovf_cnt;                 // 0 in practice
    if (oc > 0) {
        if (oc > OVFCAP) oc = OVFCAP;
        for (int k = s; k < oc; k += 2) {
            int2 e = g_ovf[k];
            if (e.x == n) {
                float4 v = h4_to_f4(__ldg(&g_y1h[e.y * 4 + q]));
                a0 += v.x; a1 += v.y; a2 += v.z; a3 += v.w;
            }
        }
    }
    // combine the two edge slots (width-8 groups)
    a0 += __shfl_down_sync(FULL, a0, 4, 8);
    a1 += __shfl_down_sync(FULL, a1, 4, 8);
    a2 += __shfl_down_sync(FULL, a2, 4, 8);
    a3 += __shfl_down_sync(FULL, a3, 4, 8);

    // lanes j=0..3 hold quarter q=j sums; partial epilogue on each
    float dinv = rsqrtf((float)(cnt + 1));
    float4 yv = h4_to_f4(g_y1h[n * 4 + q]);
    float h0 = tanh_ap(dinv * (a0 + yv.x) + sb1[4 * q + 0]);
    float h1 = tanh_ap(dinv * (a1 + yv.y) + sb1[4 * q + 1]);
    float h2 = tanh_ap(dinv * (a2 + yv.z) + sb1[4 * q + 2]);
    float h3 = tanh_ap(dinv * (a3 + yv.w) + sb1[4 * q + 3]);

    float o0, o1, o2, o3;
    {
        const float* w0 = &sW2[(4 * q + 0) * F2];
        const float* w1 = &sW2[(4 * q + 1) * F2];
        const float* w2 = &sW2[(4 * q + 2) * F2];
        const float* w3 = &sW2[(4 * q + 3) * F2];
        o0 = fmaf(h0, w0[0], fmaf(h1, w1[0], fmaf(h2, w2[0], h3 * w3[0])));
        o1 = fmaf(h0, w0[1], fmaf(h1, w1[1], fmaf(h2, w2[1], h3 * w3[1])));
        o2 = fmaf(h0, w0[2], fmaf(h1, w1[2], fmaf(h2, w2[2], h3 * w3[2])));
        o3 = fmaf(h0, w0[3], fmaf(h1, w1[3], fmaf(h2, w2[3], h3 * w3[3])));
    }
    // reduce partials across the 4 quarter-lanes
    o0 += __shfl_down_sync(FULL, o0, 2, 4);
    o1 += __shfl_down_sync(FULL, o1, 2, 4);
    o2 += __shfl_down_sync(FULL, o2, 2, 4);
    o3 += __shfl_down_sync(FULL, o3, 2, 4);
    o0 += __shfl_down_sync(FULL, o0, 1, 4);
    o1 += __shfl_down_sync(FULL, o1, 1, 4);
    o2 += __shfl_down_sync(FULL, o2, 1, 4);
    o3 += __shfl_down_sync(FULL, o3, 1, 4);

    if (j == 0)
        g_y2h[n] = f4_to_h4(o0 * dinv, o1 * dinv, o2 * dinv, o3 * dinv);
}

// ---------------- K4: pull layer-2 + fused + @W3 (PDL) ---------------------
__global__ void k_pull2(const float* __restrict__ b2, const float* __restrict__ W3) {
    __shared__ float sW3[F2 * F3];
    __shared__ float sb2[F2];
    for (int i = threadIdx.x; i < F2 * F3; i += blockDim.x) sW3[i] = W3[i];
    for (int i = threadIdx.x; i < F2; i += blockDim.x) sb2[i] = b2[i];
    __syncthreads();
    cudaGridDependencySynchronize();

    int t = blockIdx.x * blockDim.x + threadIdx.x;
    int n = t >> 2;
    int j = t & 3;
    if (n >= N_NODES) return;

    int cnt = g_cnt[n];
    int lim = min(cnt, CAP);
    int off = n * CAP;
    float a0 = 0.0f, a1 = 0.0f, a2 = 0.0f, a3 = 0.0f;
    float c0 = 0.0f, c1 = 0.0f, c2 = 0.0f, c3 = 0.0f;
    int i = off + j;
    int end = off + lim;
    for (; i + 4 < end; i += 8) {
        int src0 = __ldg(&g_pcsr[i]);
        int src1 = __ldg(&g_pcsr[i + 4]);
        float4 v0 = h4_to_f4(__ldg(&g_y2h[src0]));
        float4 v1 = h4_to_f4(__ldg(&g_y2h[src1]));
        a0 += v0.x; a1 += v0.y; a2 += v0.z; a3 += v0.w;
        c0 += v1.x; c1 += v1.y; c2 += v1.z; c3 += v1.w;
    }
    if (i < end) {
        int src = __ldg(&g_pcsr[i]);
        float4 v = h4_to_f4(__ldg(&g_y2h[src]));
        a0 += v.x; a1 += v.y; a2 += v.z; a3 += v.w;
    }
    a0 += c0; a1 += c1; a2 += c2; a3 += c3;

    int oc = g_ovf_cnt;
    if (oc > 0) {
        if (oc > OVFCAP) oc = OVFCAP;
        for (int k = j; k < oc; k += 4) {
            int2 e = g_ovf[k];
            if (e.x == n) {
                float4 v = h4_to_f4(__ldg(&g_y2h[e.y]));
                a0 += v.x; a1 += v.y; a2 += v.z; a3 += v.w;
            }
        }
    }
#pragma unroll
    for (int d = 2; d >= 1; d >>= 1) {
        a0 += __shfl_down_sync(FULL, a0, d, 4);
        a1 += __shfl_down_sync(FULL, a1, d, 4);
        a2 += __shfl_down_sync(FULL, a2, d, 4);
        a3 += __shfl_down_sync(FULL, a3, d, 4);
    }
    if (j == 0) {
        float dinv = rsqrtf((float)(cnt + 1));
        float4 yv = h4_to_f4(g_y2h[n]);
        float h0 = tanh_ap(dinv * (a0 + yv.x) + sb2[0]);
        float h1 = tanh_ap(dinv * (a1 + yv.y) + sb2[1]);
        float h2 = tanh_ap(dinv * (a2 + yv.z) + sb2[2]);
        float h3 = tanh_ap(dinv * (a3 + yv.w) + sb2[3]);
        float o0 = fmaf(h0, sW3[0], fmaf(h1, sW3[2], fmaf(h2, sW3[4], h3 * sW3[6])));
        float o1 = fmaf(h0, sW3[1], fmaf(h1, sW3[3], fmaf(h2, sW3[5], h3 * sW3[7])));
        g_y3[n] = make_float2(o0 * dinv, o1 * dinv);
    }
}

// ---------------- K5: pull layer-3 + classifier (PDL, self-cleaning) -------
// d_out layout: out[100000,8] then h3[100000,2]. Re-zeros g_cnt / g_ovf_cnt.
__global__ void k_pull3(const float* __restrict__ b3, const float* __restrict__ Wc,
                        const float* __restrict__ bc, float* __restrict__ out) {
    __shared__ float sWc[F3 * NC];
    __shared__ float sbc[NC];
    __shared__ float sb3[F3];
    for (int i = threadIdx.x; i < F3 * NC; i += blockDim.x) sWc[i] = Wc[i];
    for (int i = threadIdx.x; i < NC; i += blockDim.x) sbc[i] = bc[i];
    for (int i = threadIdx.x; i < F3; i += blockDim.x) sb3[i] = b3[i];
    __syncthreads();
    cudaGridDependencySynchronize();

    int t = blockIdx.x * blockDim.x + threadIdx.x;
    int n = t >> 2;
    int j = t & 3;
    if (n >= N_NODES) return;

    int cnt = g_cnt[n];
    int lim = min(cnt, CAP);
    int off = n * CAP;
    float a0 = 0.0f, a1 = 0.0f, c0 = 0.0f, c1 = 0.0f;
    int i = off + j;
    int end = off + lim;
    for (; i + 4 < end; i += 8) {
        int src0 = __ldg(&g_pcsr[i]);
        int src1 = __ldg(&g_pcsr[i + 4]);
        float2 v0 = g_y3[src0];
        float2 v1 = g_y3[src1];
        a0 += v0.x; a1 += v0.y;
        c0 += v1.x; c1 += v1.y;
    }
    if (i < end) {
        int src = __ldg(&g_pcsr[i]);
        float2 v = g_y3[src];
        a0 += v.x; a1 += v.y;
    }
    a0 += c0; a1 += c1;

    int oc = g_ovf_cnt;
    if (oc > 0) {
        if (oc > OVFCAP) oc = OVFCAP;
        for (int k = j; k < oc; k += 4) {
            int2 e = g_ovf[k];
            if (e.x == n) {
                float2 v = g_y3[e.y];
                a0 += v.x; a1 += v.y;
            }
        }
    }
#pragma unroll
    for (int d = 2; d >= 1; d >>= 1) {
        a0 += __shfl_down_sync(FULL, a0, d, 4);
        a1 += __shfl_down_sync(FULL, a1, d, 4);
    }
    if (j == 0) {
        g_cnt[n] = 0;
        if (n == 0) g_ovf_cnt = 0;

        float dinv = rsqrtf((float)(cnt + 1));
        float2 yv = g_y3[n];
        float h3x = tanh_ap(dinv * (a0 + yv.x) + sb3[0]);
        float h3y = tanh_ap(dinv * (a1 + yv.y) + sb3[1]);

        float o[NC];
#pragma unroll
        for (int k = 0; k < NC; k++)
            o[k] = fmaf(h3x, sWc[k], fmaf(h3y, sWc[NC + k], sbc[k]));

        float4* op = reinterpret_cast<float4*>(out + (size_t)n * NC);
        op[0] = make_float4(o[0], o[1], o[2], o[3]);
        op[1] = make_float4(o[4], o[5], o[6], o[7]);
        *reinterpret_cast<float2*>(out + (size_t)N_NODES * NC + (size_t)n * F3) =
            make_float2(h3x, h3y);
    }
}

// ---------------- host ------------------------------------------------------
template <typename... Args>
static void launch_pdl(void (*kern)(Args...), int grid, int block, Args... args) {
    cudaLaunchConfig_t cfg = {};
    cfg.gridDim = dim3(grid, 1, 1);
    cfg.blockDim = dim3(block, 1, 1);
    cfg.dynamicSmemBytes = 0;
    cfg.stream = 0;
    cudaLaunchAttribute attr[1];
    attr[0].id = cudaLaunchAttributeProgrammaticStreamSerialization;
    attr[0].val.programmaticStreamSerializationAllowed = 1;
    cfg.attrs = attr;
    cfg.numAttrs = 1;
    cudaLaunchKernelEx(&cfg, kern, args...);
}

extern "C" void kernel_launch(void* const* d_in, const int* in_sizes, int n_in,
                              void* d_out, int out_size) {
    const float* h  = (const float*)d_in[0];
    const void*  ei = d_in[1];
    const float* W1 = (const float*)d_in[2];
    const float* b1 = (const float*)d_in[3];
    const float* W2 = (const float*)d_in[4];
    const float* b2 = (const float*)d_in[5];
    const float* W3 = (const float*)d_in[6];
    const float* b3 = (const float*)d_in[7];
    const float* Wc = (const float*)d_in[8];
    const float* bc = (const float*)d_in[9];
    float* out = (float*)d_out;

    // linear 5-node chain, edges+gemm fused spatially, PDL on all dependents
    k_prep<<<EBLK + GBLK, T>>>(ei, h, W1);
    launch_pdl(k_scale, (N_NODES * 2 + T - 1) / T, T);
    launch_pdl(k_pull1, (N_NODES * 8) / T, T, b1, W2);
    launch_pdl(k_pull2, (N_NODES * 4 + T - 1) / T, T, b2, W3);
    launch_pdl(k_pull3, (N_NODES * 4 + T - 1) / T, T, b3, Wc, bc, out);
}

// round 16
// speedup vs baseline: 1.1255x; 1.1255x over previous
#include <cuda_runtime.h>
#include <cuda_fp16.h>

#define N_NODES 100000
#define N_EDGES 3200000
#define NFEAT   128
#define F1      16
#define F2      4
#define F3      2
#define NC      8
#define CAP     64           // padded CSR row capacity (deg ~ Poisson(32))
#define OVFCAP  8192
#define FULL    0xffffffffu

// ---------------- scratch (device globals; no allocation allowed) ----------
// g_cnt / g_ovf_cnt are zero at module load and re-zeroed by k_pull3 each run.
__device__ int g_ovf_cnt;
__device__ __align__(16) int    g_cnt[N_NODES];
__device__ __align__(16) int    g_pcsr[N_NODES * CAP];   // padded CSR: src ids
__device__ __align__(16) int2   g_ovf[OVFCAP];           // (dst, src) overflow
__device__ __align__(16) float  g_y1raw[N_NODES * F1];   // h@W1 (fp32, unscaled)
__device__ __align__(16) uint2  g_y1h[N_NODES * 4];      // (h@W1)*dinv, fp16
__device__ __align__(16) uint2  g_y2h[N_NODES];          // xw2*dinv, fp16
__device__ __align__(16) float2 g_y3[N_NODES];           // xw3*dinv, fp32

__device__ __forceinline__ float tanh_ap(float x) {
    float y;
    asm("tanh.approx.f32 %0, %1;" : "=f"(y) : "f"(x));
    return y;
}
__device__ __forceinline__ float4 h4_to_f4(uint2 r) {
    __half2 p0 = *reinterpret_cast<__half2*>(&r.x);
    __half2 p1 = *reinterpret_cast<__half2*>(&r.y);
    float2 f0 = __half22float2(p0);
    float2 f1 = __half22float2(p1);
    return make_float4(f0.x, f0.y, f1.x, f1.y);
}
__device__ __forceinline__ uint2 f4_to_h4(float a, float b, float c, float d) {
    __half2 p0 = __floats2half2_rn(a, b);
    __half2 p1 = __floats2half2_rn(c, d);
    uint2 r;
    r.x = *reinterpret_cast<unsigned*>(&p0);
    r.y = *reinterpret_cast<unsigned*>(&p1);
    return r;
}

// ---------------- K1: padded-CSR build with inline dtype detect -------------
__global__ void k_edges(const void* __restrict__ ei) {
    unsigned nz = 0;
    {
        const unsigned* w = (const unsigned*)ei;
        for (int k = threadIdx.x; k < 2048; k += blockDim.x) nz |= w[2 * k + 1];
    }
    int is64 = !__syncthreads_or(nz != 0);

    int e4 = blockIdx.x * blockDim.x + threadIdx.x;   // N_EDGES/4 threads
    if (e4 >= N_EDGES / 4) return;
    int s0, s1, s2, s3, d0, d1, d2, d3;
    if (is64) {
        const longlong2* ps = (const longlong2*)ei;
        const longlong2* pd = ps + N_EDGES / 2;
        longlong2 a = ps[2 * e4], b = ps[2 * e4 + 1];
        longlong2 c = pd[2 * e4], d = pd[2 * e4 + 1];
        s0 = (int)a.x; s1 = (int)a.y; s2 = (int)b.x; s3 = (int)b.y;
        d0 = (int)c.x; d1 = (int)c.y; d2 = (int)d.x; d3 = (int)d.y;
    } else {
        const int4* ps = (const int4*)ei;
        const int4* pd = ps + N_EDGES / 4;
        int4 a = ps[e4], c = pd[e4];
        s0 = a.x; s1 = a.y; s2 = a.z; s3 = a.w;
        d0 = c.x; d1 = c.y; d2 = c.z; d3 = c.w;
    }
    int r0 = atomicAdd(&g_cnt[d0], 1);
    int r1 = atomicAdd(&g_cnt[d1], 1);
    int r2 = atomicAdd(&g_cnt[d2], 1);
    int r3 = atomicAdd(&g_cnt[d3], 1);
#define PUT(S, D, R) do {                                       \
        if ((R) < CAP) g_pcsr[(D) * CAP + (R)] = (S);           \
        else {                                                  \
            int q = atomicAdd(&g_ovf_cnt, 1);                   \
            if (q < OVFCAP) g_ovf[q] = make_int2(D, S);         \
        } } while (0)
    PUT(s0, d0, r0); PUT(s1, d1, r1); PUT(s2, d2, r2); PUT(s3, d3, r3);
#undef PUT
}

// ---------------- K2 (parallel stream): y1raw = h @ W1 ----------------------
__global__ void k_gemm(const float* __restrict__ h, const float* __restrict__ W1) {
    __shared__ float sW[NFEAT * F1];   // 8 KB
    for (int i = threadIdx.x; i < NFEAT * F1; i += blockDim.x) sW[i] = W1[i];
    __syncthreads();

    int n = blockIdx.x * blockDim.x + threadIdx.x;
    if (n >= N_NODES) return;

    float acc[F1];
#pragma unroll
    for (int f = 0; f < F1; f++) acc[f] = 0.0f;

    const float4* h4 = reinterpret_cast<const float4*>(h + (size_t)n * NFEAT);
#pragma unroll 4
    for (int k4 = 0; k4 < NFEAT / 4; k4++) {
        float4 hv = h4[k4];
        const float* w = &sW[(k4 * 4) * F1];
#pragma unroll
        for (int f = 0; f < F1; f++) {
            float a = acc[f];
            a = fmaf(hv.x, w[f],          a);
            a = fmaf(hv.y, w[F1 + f],     a);
            a = fmaf(hv.z, w[2 * F1 + f], a);
            a = fmaf(hv.w, w[3 * F1 + f], a);
            acc[f] = a;
        }
    }
    float4* o = reinterpret_cast<float4*>(g_y1raw + n * F1);
#pragma unroll
    for (int q = 0; q < F1 / 4; q++)
        o[q] = make_float4(acc[4 * q], acc[4 * q + 1], acc[4 * q + 2], acc[4 * q + 3]);
}

// ---------------- K3 (join): y1h = fp16(y1raw * dinv), 2 threads/node -------
__global__ void k_scale() {
    int t = blockIdx.x * blockDim.x + threadIdx.x;   // 2*N_NODES threads
    int n = t >> 1;
    int hh = t & 1;
    if (n >= N_NODES) return;
    float dinv = rsqrtf((float)(g_cnt[n] + 1));
    const float4* r = reinterpret_cast<const float4*>(g_y1raw + n * F1 + hh * 8);
    float4 v0 = r[0];
    float4 v1 = r[1];
    g_y1h[n * 4 + hh * 2 + 0] = f4_to_h4(v0.x * dinv, v0.y * dinv, v0.z * dinv, v0.w * dinv);
    g_y1h[n * 4 + hh * 2 + 1] = f4_to_h4(v1.x * dinv, v1.y * dinv, v1.z * dinv, v1.w * dinv);
}

// ---------------- K4: pull layer-1 + fused (tanh) + @W2 (PDL secondary) ----
// 8 lanes per node = 2 edge-slots x 4 feature-quarters; fp16 gathers, unroll2.
__global__ void k_pull1(const float* __restrict__ b1, const float* __restrict__ W2) {
    __shared__ float sW2[F1 * F2];
    __shared__ float sb1[F1];
    for (int i = threadIdx.x; i < F1 * F2; i += blockDim.x) sW2[i] = W2[i];
    for (int i = threadIdx.x; i < F1; i += blockDim.x) sb1[i] = b1[i];
    __syncthreads();
    cudaGridDependencySynchronize();

    int t = blockIdx.x * blockDim.x + threadIdx.x;   // exactly N_NODES*8 threads
    int n = t >> 3;
    int j = t & 7;
    int s = j >> 2;       // edge slot 0/1
    int q = j & 3;        // feature quarter

    int cnt = g_cnt[n];
    int lim = min(cnt, CAP);
    int off = n * CAP;

    float a0 = 0.0f, a1 = 0.0f, a2 = 0.0f, a3 = 0.0f;
    float b0 = 0.0f, b1r = 0.0f, b2r = 0.0f, b3r = 0.0f;
    int i = off + s;
    int end = off + lim;
    for (; i + 2 < end; i += 4) {
        int src0 = __ldg(&g_pcsr[i]);
        int src1 = __ldg(&g_pcsr[i + 2]);
        float4 v0 = h4_to_f4(__ldg(&g_y1h[src0 * 4 + q]));
        float4 v1 = h4_to_f4(__ldg(&g_y1h[src1 * 4 + q]));
        a0 += v0.x; a1 += v0.y; a2 += v0.z; a3 += v0.w;
        b0 += v1.x; b1r += v1.y; b2r += v1.z; b3r += v1.w;
    }
    if (i < end) {
        int src = __ldg(&g_pcsr[i]);
        float4 v = h4_to_f4(__ldg(&g_y1h[src * 4 + q]));
        a0 += v.x; a1 += v.y; a2 += v.z; a3 += v.w;
    }
    a0 += b0; a1 += b1r; a2 += b2r; a3 += b3r;

    int oc = g_ovf_cnt;                 // 0 in practice
    if (oc > 0) {
        if (oc > OVFCAP) oc = OVFCAP;
        for (int k = s; k < oc; k += 2) {
            int2 e = g_ovf[k];
            if (e.x == n) {
                float4 v = h4_to_f4(__ldg(&g_y1h[e.y * 4 + q]));
                a0 += v.x; a1 += v.y; a2 += v.z; a3 += v.w;
            }
        }
    }
    // combine the two edge slots (width-8 groups)
    a0 += __shfl_down_sync(FULL, a0, 4, 8);
    a1 += __shfl_down_sync(FULL, a1, 4, 8);
    a2 += __shfl_down_sync(FULL, a2, 4, 8);
    a3 += __shfl_down_sync(FULL, a3, 4, 8);

    // lanes j=0..3 hold quarter q=j sums; partial epilogue on each
    float dinv = rsqrtf((float)(cnt + 1));
    float4 yv = h4_to_f4(g_y1h[n * 4 + q]);
    float h0 = tanh_ap(dinv * (a0 + yv.x) + sb1[4 * q + 0]);
    float h1 = tanh_ap(dinv * (a1 + yv.y) + sb1[4 * q + 1]);
    float h2 = tanh_ap(dinv * (a2 + yv.z) + sb1[4 * q + 2]);
    float h3 = tanh_ap(dinv * (a3 + yv.w) + sb1[4 * q + 3]);

    float o0, o1, o2, o3;
    {
        const float* w0 = &sW2[(4 * q + 0) * F2];
        const float* w1 = &sW2[(4 * q + 1) * F2];
        const float* w2 = &sW2[(4 * q + 2) * F2];
        const float* w3 = &sW2[(4 * q + 3) * F2];
        o0 = fmaf(h0, w0[0], fmaf(h1, w1[0], fmaf(h2, w2[0], h3 * w3[0])));
        o1 = fmaf(h0, w0[1], fmaf(h1, w1[1], fmaf(h2, w2[1], h3 * w3[1])));
        o2 = fmaf(h0, w0[2], fmaf(h1, w1[2], fmaf(h2, w2[2], h3 * w3[2])));
        o3 = fmaf(h0, w0[3], fmaf(h1, w1[3], fmaf(h2, w2[3], h3 * w3[3])));
    }
    // reduce partials across the 4 quarter-lanes
    o0 += __shfl_down_sync(FULL, o0, 2, 4);
    o1 += __shfl_down_sync(FULL, o1, 2, 4);
    o2 += __shfl_down_sync(FULL, o2, 2, 4);
    o3 += __shfl_down_sync(FULL, o3, 2, 4);
    o0 += __shfl_down_sync(FULL, o0, 1, 4);
    o1 += __shfl_down_sync(FULL, o1, 1, 4);
    o2 += __shfl_down_sync(FULL, o2, 1, 4);
    o3 += __shfl_down_sync(FULL, o3, 1, 4);

    if (j == 0)
        g_y2h[n] = f4_to_h4(o0 * dinv, o1 * dinv, o2 * dinv, o3 * dinv);
}

// ---------------- K5: pull layer-2 + fused + @W3 (8 lanes/node, PDL) -------
__global__ void k_pull2(const float* __restrict__ b2, const float* __restrict__ W3) {
    __shared__ float sW3[F2 * F3];
    __shared__ float sb2[F2];
    for (int i = threadIdx.x; i < F2 * F3; i += blockDim.x) sW3[i] = W3[i];
    for (int i = threadIdx.x; i < F2; i += blockDim.x) sb2[i] = b2[i];
    __syncthreads();
    cudaGridDependencySynchronize();

    int t = blockIdx.x * blockDim.x + threadIdx.x;   // N_NODES*8 threads
    int n = t >> 3;
    int j = t & 7;

    int cnt = g_cnt[n];
    int lim = min(cnt, CAP);
    int off = n * CAP;
    float a0 = 0.0f, a1 = 0.0f, a2 = 0.0f, a3 = 0.0f;
    for (int i = off + j, end = off + lim; i < end; i += 8) {
        int src = __ldg(&g_pcsr[i]);
        float4 v = h4_to_f4(__ldg(&g_y2h[src]));
        a0 += v.x; a1 += v.y; a2 += v.z; a3 += v.w;
    }
    int oc = g_ovf_cnt;
    if (oc > 0) {
        if (oc > OVFCAP) oc = OVFCAP;
        for (int k = j; k < oc; k += 8) {
            int2 e = g_ovf[k];
            if (e.x == n) {
                float4 v = h4_to_f4(__ldg(&g_y2h[e.y]));
                a0 += v.x; a1 += v.y; a2 += v.z; a3 += v.w;
            }
        }
    }
#pragma unroll
    for (int d = 4; d >= 1; d >>= 1) {
        a0 += __shfl_down_sync(FULL, a0, d, 8);
        a1 += __shfl_down_sync(FULL, a1, d, 8);
        a2 += __shfl_down_sync(FULL, a2, d, 8);
        a3 += __shfl_down_sync(FULL, a3, d, 8);
    }
    if (j == 0) {
        float dinv = rsqrtf((float)(cnt + 1));
        float4 yv = h4_to_f4(g_y2h[n]);
        float h0 = tanh_ap(dinv * (a0 + yv.x) + sb2[0]);
        float h1 = tanh_ap(dinv * (a1 + yv.y) + sb2[1]);
        float h2 = tanh_ap(dinv * (a2 + yv.z) + sb2[2]);
        float h3 = tanh_ap(dinv * (a3 + yv.w) + sb2[3]);
        float o0 = fmaf(h0, sW3[0], fmaf(h1, sW3[2], fmaf(h2, sW3[4], h3 * sW3[6])));
        float o1 = fmaf(h0, sW3[1], fmaf(h1, sW3[3], fmaf(h2, sW3[5], h3 * sW3[7])));
        g_y3[n] = make_float2(o0 * dinv, o1 * dinv);
    }
}

// ---------------- K6: pull layer-3 + classifier (8 lanes/node, PDL) --------
// d_out layout: out[100000,8] then h3[100000,2]. Re-zeros g_cnt / g_ovf_cnt.
__global__ void k_pull3(const float* __restrict__ b3, const float* __restrict__ Wc,
                        const float* __restrict__ bc, float* __restrict__ out) {
    __shared__ float sWc[F3 * NC];
    __shared__ float sbc[NC];
    __shared__ float sb3[F3];
    for (int i = threadIdx.x; i < F3 * NC; i += blockDim.x) sWc[i] = Wc[i];
    for (int i = threadIdx.x; i < NC; i += blockDim.x) sbc[i] = bc[i];
    for (int i = threadIdx.x; i < F3; i += blockDim.x) sb3[i] = b3[i];
    __syncthreads();
    cudaGridDependencySynchronize();

    int t = blockIdx.x * blockDim.x + threadIdx.x;   // N_NODES*8 threads
    int n = t >> 3;
    int j = t & 7;

    int cnt = g_cnt[n];
    int lim = min(cnt, CAP);
    int off = n * CAP;
    float a0 = 0.0f, a1 = 0.0f;
    for (int i = off + j, end = off + lim; i < end; i += 8) {
        int src = __ldg(&g_pcsr[i]);
        float2 v = g_y3[src];
        a0 += v.x; a1 += v.y;
    }
    int oc = g_ovf_cnt;
    if (oc > 0) {
        if (oc > OVFCAP) oc = OVFCAP;
        for (int k = j; k < oc; k += 8) {
            int2 e = g_ovf[k];
            if (e.x == n) {
                float2 v = g_y3[e.y];
                a0 += v.x; a1 += v.y;
            }
        }
    }
#pragma unroll
    for (int d = 4; d >= 1; d >>= 1) {
        a0 += __shfl_down_sync(FULL, a0, d, 8);
        a1 += __shfl_down_sync(FULL, a1, d, 8);
    }
    if (j == 0) {
        g_cnt[n] = 0;
        if (n == 0) g_ovf_cnt = 0;

        float dinv = rsqrtf((float)(cnt + 1));
        float2 yv = g_y3[n];
        float h3x = tanh_ap(dinv * (a0 + yv.x) + sb3[0]);
        float h3y = tanh_ap(dinv * (a1 + yv.y) + sb3[1]);

        float o[NC];
#pragma unroll
        for (int k = 0; k < NC; k++)
            o[k] = fmaf(h3x, sWc[k], fmaf(h3y, sWc[NC + k], sbc[k]));

        float4* op = reinterpret_cast<float4*>(out + (size_t)n * NC);
        op[0] = make_float4(o[0], o[1], o[2], o[3]);
        op[1] = make_float4(o[4], o[5], o[6], o[7]);
        *reinterpret_cast<float2*>(out + (size_t)N_NODES * NC + (size_t)n * F3) =
            make_float2(h3x, h3y);
    }
}

// ---------------- host ------------------------------------------------------
template <typename... Args>
static void launch_pdl(void (*kern)(Args...), int grid, int block,
                       cudaStream_t st, Args... args) {
    cudaLaunchConfig_t cfg = {};
    cfg.gridDim = dim3(grid, 1, 1);
    cfg.blockDim = dim3(block, 1, 1);
    cfg.dynamicSmemBytes = 0;
    cfg.stream = st;
    cudaLaunchAttribute attr[1];
    attr[0].id = cudaLaunchAttributeProgrammaticStreamSerialization;
    attr[0].val.programmaticStreamSerializationAllowed = 1;
    cfg.attrs = attr;
    cfg.numAttrs = 1;
    cudaLaunchKernelEx(&cfg, kern, args...);
}

extern "C" void kernel_launch(void* const* d_in, const int* in_sizes, int n_in,
                              void* d_out, int out_size) {
    const float* h  = (const float*)d_in[0];
    const void*  ei = d_in[1];
    const float* W1 = (const float*)d_in[2];
    const float* b1 = (const float*)d_in[3];
    const float* W2 = (const float*)d_in[4];
    const float* b2 = (const float*)d_in[5];
    const float* W3 = (const float*)d_in[6];
    const float* b3 = (const float*)d_in[7];
    const float* Wc = (const float*)d_in[8];
    const float* bc = (const float*)d_in[9];
    float* out = (float*)d_out;

    const int T = 256;

    // fork a side stream for the edge-independent GEMM (capture-legal pattern).
    cudaStream_t s2;
    cudaEvent_t eF, eJ;
    cudaStreamCreateWithFlags(&s2, cudaStreamNonBlocking);
    cudaEventCreateWithFlags(&eF, cudaEventDisableTiming);
    cudaEventCreateWithFlags(&eJ, cudaEventDisableTiming);

    cudaEventRecord(eF, 0);
    cudaStreamWaitEvent(s2, eF, 0);
    k_gemm<<<(N_NODES + T - 1) / T, T, 0, s2>>>(h, W1);     // ∥ with edge build
    cudaEventRecord(eJ, s2);

    k_edges <<<(N_EDGES / 4 + T - 1) / T, T>>>(ei);

    cudaStreamWaitEvent(0, eJ, 0);                          // join
    k_scale <<<(N_NODES * 2 + T - 1) / T, T>>>();

    // dependent chain with programmatic (PDL) launches — each kernel stages
    // weights pre-sync, then cudaGridDependencySynchronize()s before g_* reads.
    launch_pdl(k_pull1, (N_NODES * 8) / T, T, (cudaStream_t)0, b1, W2);
    launch_pdl(k_pull2, (N_NODES * 8) / T, T, (cudaStream_t)0, b2, W3);
    launch_pdl(k_pull3, (N_NODES * 8) / T, T, (cudaStream_t)0, b3, Wc, bc, out);
}

// round 17
// speedup vs baseline: 1.1832x; 1.0513x over previous
#include <cuda_runtime.h>
#include <cuda_fp16.h>

#define N_NODES 100000
#define N_EDGES 3200000
#define NFEAT   128
#define F1      16
#define F2      4
#define F3      2
#define NC      8
#define CAP     64           // padded CSR row capacity (deg ~ Poisson(32))
#define OVFCAP  8192
#define FULL    0xffffffffu

// ---------------- scratch (device globals; no allocation allowed) ----------
// g_cnt / g_ovf_cnt are zero at module load and re-zeroed by k_pull3 each run.
__device__ int g_ovf_cnt;
__device__ __align__(16) int    g_cnt[N_NODES];
__device__ __align__(16) int    g_pcsr[N_NODES * CAP];   // padded CSR: src ids
__device__ __align__(16) int2   g_ovf[OVFCAP];           // (dst, src) overflow
__device__ __align__(16) float  g_y1raw[N_NODES * F1];   // h@W1 (fp32, unscaled)
__device__ __align__(16) uint2  g_y1h[N_NODES * 4];      // (h@W1)*dinv, fp16
__device__ __align__(16) uint2  g_y2h[N_NODES];          // xw2*dinv, fp16
__device__ __align__(16) float2 g_y3[N_NODES];           // xw3*dinv, fp32

__device__ __forceinline__ float tanh_ap(float x) {
    float y;
    asm("tanh.approx.f32 %0, %1;" : "=f"(y) : "f"(x));
    return y;
}
__device__ __forceinline__ float4 h4_to_f4(uint2 r) {
    __half2 p0 = *reinterpret_cast<__half2*>(&r.x);
    __half2 p1 = *reinterpret_cast<__half2*>(&r.y);
    float2 f0 = __half22float2(p0);
    float2 f1 = __half22float2(p1);
    return make_float4(f0.x, f0.y, f1.x, f1.y);
}
__device__ __forceinline__ uint2 f4_to_h4(float a, float b, float c, float d) {
    __half2 p0 = __floats2half2_rn(a, b);
    __half2 p1 = __floats2half2_rn(c, d);
    uint2 r;
    r.x = *reinterpret_cast<unsigned*>(&p0);
    r.y = *reinterpret_cast<unsigned*>(&p1);
    return r;
}

// ---------------- K1: padded-CSR build with inline dtype detect -------------
// Detect: 1 odd-word per thread (256 words, 1KB). P(false int64 | int32 data)
// = P(word==0)^256 ~ 1e-1280 — statistically impossible.
__global__ void k_edges(const void* __restrict__ ei) {
    unsigned nz = ((const unsigned*)ei)[2 * threadIdx.x + 1];
    int is64 = !__syncthreads_or(nz != 0);

    int e4 = blockIdx.x * blockDim.x + threadIdx.x;   // N_EDGES/4 threads
    if (e4 >= N_EDGES / 4) return;
    int s0, s1, s2, s3, d0, d1, d2, d3;
    if (is64) {
        const longlong2* ps = (const longlong2*)ei;
        const longlong2* pd = ps + N_EDGES / 2;
        longlong2 a = ps[2 * e4], b = ps[2 * e4 + 1];
        longlong2 c = pd[2 * e4], d = pd[2 * e4 + 1];
        s0 = (int)a.x; s1 = (int)a.y; s2 = (int)b.x; s3 = (int)b.y;
        d0 = (int)c.x; d1 = (int)c.y; d2 = (int)d.x; d3 = (int)d.y;
    } else {
        const int4* ps = (const int4*)ei;
        const int4* pd = ps + N_EDGES / 4;
        int4 a = ps[e4], c = pd[e4];
        s0 = a.x; s1 = a.y; s2 = a.z; s3 = a.w;
        d0 = c.x; d1 = c.y; d2 = c.z; d3 = c.w;
    }
    int r0 = atomicAdd(&g_cnt[d0], 1);
    int r1 = atomicAdd(&g_cnt[d1], 1);
    int r2 = atomicAdd(&g_cnt[d2], 1);
    int r3 = atomicAdd(&g_cnt[d3], 1);
#define PUT(S, D, R) do {                                       \
        if ((R) < CAP) g_pcsr[(D) * CAP + (R)] = (S);           \
        else {                                                  \
            int q = atomicAdd(&g_ovf_cnt, 1);                   \
            if (q < OVFCAP) g_ovf[q] = make_int2(D, S);         \
        } } while (0)
    PUT(s0, d0, r0); PUT(s1, d1, r1); PUT(s2, d2, r2); PUT(s3, d3, r3);
#undef PUT
}

// ---------------- K2 (parallel stream): y1raw = h @ W1 ----------------------
__global__ void k_gemm(const float* __restrict__ h, const float* __restrict__ W1) {
    __shared__ float sW[NFEAT * F1];   // 8 KB
    for (int i = threadIdx.x; i < NFEAT * F1; i += blockDim.x) sW[i] = W1[i];
    __syncthreads();

    int n = blockIdx.x * blockDim.x + threadIdx.x;
    if (n >= N_NODES) return;

    float acc[F1];
#pragma unroll
    for (int f = 0; f < F1; f++) acc[f] = 0.0f;

    const float4* h4 = reinterpret_cast<const float4*>(h + (size_t)n * NFEAT);
#pragma unroll 4
    for (int k4 = 0; k4 < NFEAT / 4; k4++) {
        float4 hv = h4[k4];
        const float* w = &sW[(k4 * 4) * F1];
#pragma unroll
        for (int f = 0; f < F1; f++) {
            float a = acc[f];
            a = fmaf(hv.x, w[f],          a);
            a = fmaf(hv.y, w[F1 + f],     a);
            a = fmaf(hv.z, w[2 * F1 + f], a);
            a = fmaf(hv.w, w[3 * F1 + f], a);
            acc[f] = a;
        }
    }
    float4* o = reinterpret_cast<float4*>(g_y1raw + n * F1);
#pragma unroll
    for (int q = 0; q < F1 / 4; q++)
        o[q] = make_float4(acc[4 * q], acc[4 * q + 1], acc[4 * q + 2], acc[4 * q + 3]);
}

// ---------------- K3 (join): y1h = fp16(y1raw * dinv), 2 threads/node -------
__global__ void k_scale() {
    int t = blockIdx.x * blockDim.x + threadIdx.x;   // 2*N_NODES threads
    int n = t >> 1;
    int hh = t & 1;
    if (n >= N_NODES) return;
    float dinv = rsqrtf((float)(g_cnt[n] + 1));
    const float4* r = reinterpret_cast<const float4*>(g_y1raw + n * F1 + hh * 8);
    float4 v0 = r[0];
    float4 v1 = r[1];
    g_y1h[n * 4 + hh * 2 + 0] = f4_to_h4(v0.x * dinv, v0.y * dinv, v0.z * dinv, v0.w * dinv);
    g_y1h[n * 4 + hh * 2 + 1] = f4_to_h4(v1.x * dinv, v1.y * dinv, v1.z * dinv, v1.w * dinv);
}

// ---------------- K4: pull layer-1 + fused (tanh) + @W2 (PDL secondary) ----
// 8 lanes per node = 2 edge-slots x 4 feature-quarters; fp16 gathers, unroll2.
__global__ void k_pull1(const float* __restrict__ b1, const float* __restrict__ W2) {
    __shared__ float sW2[F1 * F2];
    __shared__ float sb1[F1];
    for (int i = threadIdx.x; i < F1 * F2; i += blockDim.x) sW2[i] = W2[i];
    for (int i = threadIdx.x; i < F1; i += blockDim.x) sb1[i] = b1[i];
    __syncthreads();
    cudaGridDependencySynchronize();

    int t = blockIdx.x * blockDim.x + threadIdx.x;   // exactly N_NODES*8 threads
    int n = t >> 3;
    int j = t & 7;
    int s = j >> 2;       // edge slot 0/1
    int q = j & 3;        // feature quarter

    int cnt = g_cnt[n];
    int lim = min(cnt, CAP);
    int off = n * CAP;

    float a0 = 0.0f, a1 = 0.0f, a2 = 0.0f, a3 = 0.0f;
    float b0 = 0.0f, b1r = 0.0f, b2r = 0.0f, b3r = 0.0f;
    int i = off + s;
    int end = off + lim;
    for (; i + 2 < end; i += 4) {
        int src0 = __ldg(&g_pcsr[i]);
        int src1 = __ldg(&g_pcsr[i + 2]);
        float4 v0 = h4_to_f4(__ldg(&g_y1h[src0 * 4 + q]));
        float4 v1 = h4_to_f4(__ldg(&g_y1h[src1 * 4 + q]));
        a0 += v0.x; a1 += v0.y; a2 += v0.z; a3 += v0.w;
        b0 += v1.x; b1r += v1.y; b2r += v1.z; b3r += v1.w;
    }
    if (i < end) {
        int src = __ldg(&g_pcsr[i]);
        float4 v = h4_to_f4(__ldg(&g_y1h[src * 4 + q]));
        a0 += v.x; a1 += v.y; a2 += v.z; a3 += v.w;
    }
    a0 += b0; a1 += b1r; a2 += b2r; a3 += b3r;

    int oc = g_ovf_cnt;                 // 0 in practice
    if (oc > 0) {
        if (oc > OVFCAP) oc = OVFCAP;
        for (int k = s; k < oc; k += 2) {
            int2 e = g_ovf[k];
            if (e.x == n) {
                float4 v = h4_to_f4(__ldg(&g_y1h[e.y * 4 + q]));
                a0 += v.x; a1 += v.y; a2 += v.z; a3 += v.w;
            }
        }
    }
    // combine the two edge slots (width-8 groups)
    a0 += __shfl_down_sync(FULL, a0, 4, 8);
    a1 += __shfl_down_sync(FULL, a1, 4, 8);
    a2 += __shfl_down_sync(FULL, a2, 4, 8);
    a3 += __shfl_down_sync(FULL, a3, 4, 8);

    // lanes j=0..3 hold quarter q=j sums; partial epilogue on each
    float dinv = rsqrtf((float)(cnt + 1));
    float4 yv = h4_to_f4(g_y1h[n * 4 + q]);
    float h0 = tanh_ap(dinv * (a0 + yv.x) + sb1[4 * q + 0]);
    float h1 = tanh_ap(dinv * (a1 + yv.y) + sb1[4 * q + 1]);
    float h2 = tanh_ap(dinv * (a2 + yv.z) + sb1[4 * q + 2]);
    float h3 = tanh_ap(dinv * (a3 + yv.w) + sb1[4 * q + 3]);

    float o0, o1, o2, o3;
    {
        const float* w0 = &sW2[(4 * q + 0) * F2];
        const float* w1 = &sW2[(4 * q + 1) * F2];
        const float* w2 = &sW2[(4 * q + 2) * F2];
        const float* w3 = &sW2[(4 * q + 3) * F2];
        o0 = fmaf(h0, w0[0], fmaf(h1, w1[0], fmaf(h2, w2[0], h3 * w3[0])));
        o1 = fmaf(h0, w0[1], fmaf(h1, w1[1], fmaf(h2, w2[1], h3 * w3[1])));
        o2 = fmaf(h0, w0[2], fmaf(h1, w1[2], fmaf(h2, w2[2], h3 * w3[2])));
        o3 = fmaf(h0, w0[3], fmaf(h1, w1[3], fmaf(h2, w2[3], h3 * w3[3])));
    }
    // reduce partials across the 4 quarter-lanes
    o0 += __shfl_down_sync(FULL, o0, 2, 4);
    o1 += __shfl_down_sync(FULL, o1, 2, 4);
    o2 += __shfl_down_sync(FULL, o2, 2, 4);
    o3 += __shfl_down_sync(FULL, o3, 2, 4);
    o0 += __shfl_down_sync(FULL, o0, 1, 4);
    o1 += __shfl_down_sync(FULL, o1, 1, 4);
    o2 += __shfl_down_sync(FULL, o2, 1, 4);
    o3 += __shfl_down_sync(FULL, o3, 1, 4);

    if (j == 0)
        g_y2h[n] = f4_to_h4(o0 * dinv, o1 * dinv, o2 * dinv, o3 * dinv);
}

// ---------------- K5: pull layer-2 + fused + @W3 (4 lanes/node, PDL) -------
__global__ void k_pull2(const float* __restrict__ b2, const float* __restrict__ W3) {
    __shared__ float sW3[F2 * F3];
    __shared__ float sb2[F2];
    for (int i = threadIdx.x; i < F2 * F3; i += blockDim.x) sW3[i] = W3[i];
    for (int i = threadIdx.x; i < F2; i += blockDim.x) sb2[i] = b2[i];
    __syncthreads();
    cudaGridDependencySynchronize();

    int t = blockIdx.x * blockDim.x + threadIdx.x;
    int n = t >> 2;
    int j = t & 3;
    if (n >= N_NODES) return;

    int cnt = g_cnt[n];
    int lim = min(cnt, CAP);
    int off = n * CAP;
    float a0 = 0.0f, a1 = 0.0f, a2 = 0.0f, a3 = 0.0f;
    float c0 = 0.0f, c1 = 0.0f, c2 = 0.0f, c3 = 0.0f;
    int i = off + j;
    int end = off + lim;
    for (; i + 4 < end; i += 8) {
        int src0 = __ldg(&g_pcsr[i]);
        int src1 = __ldg(&g_pcsr[i + 4]);
        float4 v0 = h4_to_f4(__ldg(&g_y2h[src0]));
        float4 v1 = h4_to_f4(__ldg(&g_y2h[src1]));
        a0 += v0.x; a1 += v0.y; a2 += v0.z; a3 += v0.w;
        c0 += v1.x; c1 += v1.y; c2 += v1.z; c3 += v1.w;
    }
    if (i < end) {
        int src = __ldg(&g_pcsr[i]);
        float4 v = h4_to_f4(__ldg(&g_y2h[src]));
        a0 += v.x; a1 += v.y; a2 += v.z; a3 += v.w;
    }
    a0 += c0; a1 += c1; a2 += c2; a3 += c3;

    int oc = g_ovf_cnt;
    if (oc > 0) {
        if (oc > OVFCAP) oc = OVFCAP;
        for (int k = j; k < oc; k += 4) {
            int2 e = g_ovf[k];
            if (e.x == n) {
                float4 v = h4_to_f4(__ldg(&g_y2h[e.y]));
                a0 += v.x; a1 += v.y; a2 += v.z; a3 += v.w;
            }
        }
    }
#pragma unroll
    for (int d = 2; d >= 1; d >>= 1) {
        a0 += __shfl_down_sync(FULL, a0, d, 4);
        a1 += __shfl_down_sync(FULL, a1, d, 4);
        a2 += __shfl_down_sync(FULL, a2, d, 4);
        a3 += __shfl_down_sync(FULL, a3, d, 4);
    }
    if (j == 0) {
        float dinv = rsqrtf((float)(cnt + 1));
        float4 yv = h4_to_f4(g_y2h[n]);
        float h0 = tanh_ap(dinv * (a0 + yv.x) + sb2[0]);
        float h1 = tanh_ap(dinv * (a1 + yv.y) + sb2[1]);
        float h2 = tanh_ap(dinv * (a2 + yv.z) + sb2[2]);
        float h3 = tanh_ap(dinv * (a3 + yv.w) + sb2[3]);
        float o0 = fmaf(h0, sW3[0], fmaf(h1, sW3[2], fmaf(h2, sW3[4], h3 * sW3[6])));
        float o1 = fmaf(h0, sW3[1], fmaf(h1, sW3[3], fmaf(h2, sW3[5], h3 * sW3[7])));
        g_y3[n] = make_float2(o0 * dinv, o1 * dinv);
    }
}

// ---------------- K6: pull layer-3 + classifier (4 lanes, PDL) -------------
// d_out layout: out[100000,8] then h3[100000,2]. Re-zeros g_cnt / g_ovf_cnt.
__global__ void k_pull3(const float* __restrict__ b3, const float* __restrict__ Wc,
                        const float* __restrict__ bc, float* __restrict__ out) {
    __shared__ float sWc[F3 * NC];
    __shared__ float sbc[NC];
    __shared__ float sb3[F3];
    for (int i = threadIdx.x; i < F3 * NC; i += blockDim.x) sWc[i] = Wc[i];
    for (int i = threadIdx.x; i < NC; i += blockDim.x) sbc[i] = bc[i];
    for (int i = threadIdx.x; i < F3; i += blockDim.x) sb3[i] = b3[i];
    __syncthreads();
    cudaGridDependencySynchronize();

    int t = blockIdx.x * blockDim.x + threadIdx.x;
    int n = t >> 2;
    int j = t & 3;
    if (n >= N_NODES) return;

    int cnt = g_cnt[n];
    int lim = min(cnt, CAP);
    int off = n * CAP;
    float a0 = 0.0f, a1 = 0.0f, c0 = 0.0f, c1 = 0.0f;
    int i = off + j;
    int end = off + lim;
    for (; i + 4 < end; i += 8) {
        int src0 = __ldg(&g_pcsr[i]);
        int src1 = __ldg(&g_pcsr[i + 4]);
        float2 v0 = g_y3[src0];
        float2 v1 = g_y3[src1];
        a0 += v0.x; a1 += v0.y;
        c0 += v1.x; c1 += v1.y;
    }
    if (i < end) {
        int src = __ldg(&g_pcsr[i]);
        float2 v = g_y3[src];
        a0 += v.x; a1 += v.y;
    }
    a0 += c0; a1 += c1;

    int oc = g_ovf_cnt;
    if (oc > 0) {
        if (oc > OVFCAP) oc = OVFCAP;
        for (int k = j; k < oc; k += 4) {
            int2 e = g_ovf[k];
            if (e.x == n) {
                float2 v = g_y3[e.y];
                a0 += v.x; a1 += v.y;
            }
        }
    }
#pragma unroll
    for (int d = 2; d >= 1; d >>= 1) {
        a0 += __shfl_down_sync(FULL, a0, d, 4);
        a1 += __shfl_down_sync(FULL, a1, d, 4);
    }
    if (j == 0) {
        g_cnt[n] = 0;
        if (n == 0) g_ovf_cnt = 0;

        float dinv = rsqrtf((float)(cnt + 1));
        float2 yv = g_y3[n];
        float h3x = tanh_ap(dinv * (a0 + yv.x) + sb3[0]);
        float h3y = tanh_ap(dinv * (a1 + yv.y) + sb3[1]);

        float o[NC];
#pragma unroll
        for (int k = 0; k < NC; k++)
            o[k] = fmaf(h3x, sWc[k], fmaf(h3y, sWc[NC + k], sbc[k]));

        float4* op = reinterpret_cast<float4*>(out + (size_t)n * NC);
        op[0] = make_float4(o[0], o[1], o[2], o[3]);
        op[1] = make_float4(o[4], o[5], o[6], o[7]);
        *reinterpret_cast<float2*>(out + (size_t)N_NODES * NC + (size_t)n * F3) =
            make_float2(h3x, h3y);
    }
}

// ---------------- host ------------------------------------------------------
template <typename... Args>
static void launch_pdl(void (*kern)(Args...), int grid, int block,
                       cudaStream_t st, Args... args) {
    cudaLaunchConfig_t cfg = {};
    cfg.gridDim = dim3(grid, 1, 1);
    cfg.blockDim = dim3(block, 1, 1);
    cfg.dynamicSmemBytes = 0;
    cfg.stream = st;
    cudaLaunchAttribute attr[1];
    attr[0].id = cudaLaunchAttributeProgrammaticStreamSerialization;
    attr[0].val.programmaticStreamSerializationAllowed = 1;
    cfg.attrs = attr;
    cfg.numAttrs = 1;
    cudaLaunchKernelEx(&cfg, kern, args...);
}

extern "C" void kernel_launch(void* const* d_in, const int* in_sizes, int n_in,
                              void* d_out, int out_size) {
    const float* h  = (const float*)d_in[0];
    const void*  ei = d_in[1];
    const float* W1 = (const float*)d_in[2];
    const float* b1 = (const float*)d_in[3];
    const float* W2 = (const float*)d_in[4];
    const float* b2 = (const float*)d_in[5];
    const float* W3 = (const float*)d_in[6];
    const float* b3 = (const float*)d_in[7];
    const float* Wc = (const float*)d_in[8];
    const float* bc = (const float*)d_in[9];
    float* out = (float*)d_out;

    const int T = 256;

    // fork a side stream for the edge-independent GEMM (capture-legal pattern).
    cudaStream_t s2;
    cudaEvent_t eF, eJ;
    cudaStreamCreateWithFlags(&s2, cudaStreamNonBlocking);
    cudaEventCreateWithFlags(&eF, cudaEventDisableTiming);
    cudaEventCreateWithFlags(&eJ, cudaEventDisableTiming);

    cudaEventRecord(eF, 0);
    cudaStreamWaitEvent(s2, eF, 0);
    k_gemm<<<(N_NODES + T - 1) / T, T, 0, s2>>>(h, W1);     // ∥ with edge build
    cudaEventRecord(eJ, s2);

    k_edges <<<(N_EDGES / 4 + T - 1) / T, T>>>(ei);

    cudaStreamWaitEvent(0, eJ, 0);                          // join
    k_scale <<<(N_NODES * 2 + T - 1) / T, T>>>();

    // dependent chain with programmatic (PDL) launches — each kernel stages
    // weights pre-sync, then cudaGridDependencySynchronize()s before g_* reads.
    launch_pdl(k_pull1, (N_NODES * 8) / T, T, (cudaStream_t)0, b1, W2);
    launch_pdl(k_pull2, (N_NODES * 4 + T - 1) / T, T, (cudaStream_t)0, b2, W3);
    launch_pdl(k_pull3, (N_NODES * 4 + T - 1) / T, T, (cudaStream_t)0, b3, Wc, bc, out);
}